// round 1
// baseline (speedup 1.0000x reference)
#include <cuda_runtime.h>

#define T 1024
#define IW 512
#define H 256
#define OW 512
#define E 64
#define NA 2048  // token-expert assignments = T*K

typedef unsigned long long u64;

// ---------------- device scratch (no allocs allowed) ----------------
__device__ __align__(16) float g_V[NA * H];      // 2 MB  relu(x@W1+b1), permuted by expert
__device__ __align__(16) float g_tmp[NA * OW];   // 4 MB  per-assignment scaled outputs
__device__ int   g_topk_idx[NA];
__device__ float g_topk_score[NA];
__device__ int   g_seg_start[E + 1];
__device__ int   g_perm_a[NA];                   // assignment id = token*2 + slot
__device__ float g_perm_score[NA];

// ---------------- packed f32x2 helpers (sm_103a) ----------------
__device__ __forceinline__ u64 pack2(float a, float b) {
    u64 r; unsigned ai = __float_as_uint(a), bi = __float_as_uint(b);
    asm("mov.b64 %0, {%1, %2};" : "=l"(r) : "r"(ai), "r"(bi));
    return r;
}
__device__ __forceinline__ void ffma2(u64 &d, u64 a, u64 b) {
    asm("fma.rn.f32x2 %0, %1, %2, %0;" : "+l"(d) : "l"(a), "l"(b));
}
__device__ __forceinline__ float2 unpack2(u64 v) {
    unsigned lo, hi;
    asm("mov.b64 {%0, %1}, %2;" : "=r"(lo), "=r"(hi) : "l"(v));
    float2 f; f.x = __uint_as_float(lo); f.y = __uint_as_float(hi);
    return f;
}

// ---------------- kernel 1: routing ----------------
// h = x@mixer + noise * softplus(x@noise_ctl); top-2; softmax over top-2.
__global__ __launch_bounds__(256) void routing_kernel(
    const float* __restrict__ x, const float* __restrict__ noise,
    const float* __restrict__ mixer, const float* __restrict__ nctl)
{
    __shared__ float xs[32 * 32];
    __shared__ float ms[32 * 64];
    __shared__ float ns[32 * 64];
    __shared__ float hs[32 * 64];
    int tid = threadIdx.x;
    int t0 = blockIdx.x * 32;
    int ee = tid & 63, tg = tid >> 6;   // thread -> expert, token-group

    float accm[8], accn[8];
#pragma unroll
    for (int j = 0; j < 8; j++) { accm[j] = 0.f; accn[j] = 0.f; }

    for (int i0 = 0; i0 < IW; i0 += 32) {
#pragma unroll
        for (int q = 0; q < 4; q++) {
            int idx = tid + 256 * q; int tt = idx >> 5, ii = idx & 31;
            xs[tt * 32 + ii] = x[(t0 + tt) * IW + i0 + ii];
        }
#pragma unroll
        for (int q = 0; q < 8; q++) {
            int idx = tid + 256 * q; int ii = idx >> 6, e2 = idx & 63;
            ms[ii * 64 + e2] = mixer[(i0 + ii) * E + e2];
            ns[ii * 64 + e2] = nctl [(i0 + ii) * E + e2];
        }
        __syncthreads();
        for (int ii = 0; ii < 32; ii++) {
            float m = ms[ii * 64 + ee], n = ns[ii * 64 + ee];
#pragma unroll
            for (int j = 0; j < 8; j++) {
                float xv = xs[(tg + 4 * j) * 32 + ii];
                accm[j] += xv * m;
                accn[j] += xv * n;
            }
        }
        __syncthreads();
    }

#pragma unroll
    for (int j = 0; j < 8; j++) {
        int t = tg + 4 * j;
        float z = accn[j];
        float sp = (z > 20.f) ? z : log1pf(expf(z));   // stable softplus
        float h = accm[j] + noise[(t0 + t) * E + ee] * sp;
        hs[t * 64 + ee] = h;
    }
    __syncthreads();

    if (tid < 32) {
        int t = tid;
        float v0 = -1e30f, v1 = -1e30f; int i0 = -1, i1 = -1;
        for (int ec = 0; ec < 64; ec++) {
            float v = hs[t * 64 + ec];
            if (v > v0)      { v1 = v0; i1 = i0; v0 = v; i0 = ec; }
            else if (v > v1) { v1 = v; i1 = ec; }
        }
        float e1 = expf(v1 - v0);            // <= 1, stable
        float s0 = 1.f / (1.f + e1);
        float s1 = e1 * s0;
        g_topk_idx[(t0 + t) * 2 + 0] = i0;
        g_topk_idx[(t0 + t) * 2 + 1] = i1;
        g_topk_score[(t0 + t) * 2 + 0] = s0;
        g_topk_score[(t0 + t) * 2 + 1] = s1;
    }
}

// ---------------- kernel 2: group assignments by expert ----------------
__global__ __launch_bounds__(256) void group_kernel()
{
    __shared__ int cnt[E];
    __shared__ int st[E + 1];
    __shared__ int cur[E];
    int tid = threadIdx.x;
    if (tid < E) cnt[tid] = 0;
    __syncthreads();
    for (int a = tid; a < NA; a += 256) atomicAdd(&cnt[g_topk_idx[a]], 1);
    __syncthreads();
    if (tid == 0) {
        int run = 0;
        for (int e2 = 0; e2 < E; e2++) { st[e2] = run; run += cnt[e2]; }
        st[E] = run;
    }
    __syncthreads();
    if (tid < E) cur[tid] = st[tid];
    if (tid <= E) g_seg_start[tid] = st[tid];
    __syncthreads();
    for (int a = tid; a < NA; a += 256) {
        int e2 = g_topk_idx[a];
        int pos = atomicAdd(&cur[e2], 1);
        g_perm_a[pos] = a;
        g_perm_score[pos] = g_topk_score[a];
    }
}

// ---------------- kernel 3: V = relu(X_e @ W1_e + b1_e) ----------------
// grid (2 h-halves, 64 experts), 256 threads. f32x2 packed over h-pairs.
__global__ __launch_bounds__(256) void ffn1_kernel(
    const float* __restrict__ w1s, const float* __restrict__ b1s,
    const float* __restrict__ x)
{
    __shared__ float ws[32 * 130];     // [i-tile 32][h 128 +2 pad]
    __shared__ float xst[32 * 33];     // [t 32][i-tile 32 +1 pad]
    __shared__ int tok[32];
    int e = blockIdx.y, hc = blockIdx.x;
    int tid = threadIdx.x;
    int s = g_seg_start[e];
    int cnt = g_seg_start[e + 1] - s;
    int t = tid & 31, grp = tid >> 5;          // 8 h-groups of 16
    int hg = hc * 128 + grp * 16;              // this thread's first h (even)

    for (int c0 = 0; c0 < cnt; c0 += 32) {
        int nt = min(32, cnt - c0);
        __syncthreads();
        if (tid < 32) tok[tid] = (tid < nt) ? (g_perm_a[s + c0 + tid] >> 1) : -1;
        __syncthreads();

        u64 acc[8];
#pragma unroll
        for (int r = 0; r < 8; r++)
            acc[r] = *(const u64*)(b1s + e * H + hg + 2 * r);

        for (int i0 = 0; i0 < IW; i0 += 32) {
#pragma unroll
            for (int q = 0; q < 16; q++) {
                int idx = tid + 256 * q; int ii = idx >> 7, hh = idx & 127;
                ws[ii * 130 + hh] =
                    w1s[((size_t)e * IW + i0 + ii) * H + hc * 128 + hh];
            }
#pragma unroll
            for (int q = 0; q < 4; q++) {
                int idx = tid + 256 * q; int tt = idx >> 5, ii = idx & 31;
                int tk = tok[tt];
                xst[tt * 33 + ii] = (tk >= 0) ? x[tk * IW + i0 + ii] : 0.f;
            }
            __syncthreads();
#pragma unroll 4
            for (int ii = 0; ii < 32; ii++) {
                float xv = xst[t * 33 + ii];
                u64 xp = pack2(xv, xv);
                const float* wrow = &ws[ii * 130 + grp * 16];
#pragma unroll
                for (int r = 0; r < 8; r++) {
                    u64 wp = *(const u64*)(wrow + 2 * r);
                    ffma2(acc[r], xp, wp);
                }
            }
            __syncthreads();
        }

        if (t < nt) {
            int row = s + c0 + t;
#pragma unroll
            for (int r = 0; r < 8; r++) {
                float2 f = unpack2(acc[r]);
                f.x = fmaxf(f.x, 0.f); f.y = fmaxf(f.y, 0.f);
                *(float2*)&g_V[(size_t)row * H + hg + 2 * r] = f;
            }
        }
    }
}

// ---------------- kernel 4: tmp = score * (V_e @ W2_e + b2_e) ----------------
// grid (2 o-halves, 64 experts), 256 threads. f32x2 packed over o-pairs.
__global__ __launch_bounds__(256) void ffn2_kernel(
    const float* __restrict__ w2s, const float* __restrict__ b2s)
{
    __shared__ float ws2[32 * 258];    // [h-tile 32][o 256 +2 pad]
    __shared__ float vst[32 * 33];     // [t 32][h-tile 32 +1 pad]
    __shared__ int sa[32];
    __shared__ float ssc[32];
    int e = blockIdx.y, oc = blockIdx.x;
    int tid = threadIdx.x;
    int s = g_seg_start[e];
    int cnt = g_seg_start[e + 1] - s;
    int t = tid & 31, grp = tid >> 5;          // 8 o-groups of 32
    int og = oc * 256 + grp * 32;

    for (int c0 = 0; c0 < cnt; c0 += 32) {
        int nt = min(32, cnt - c0);
        __syncthreads();
        if (tid < 32) {
            bool v = tid < nt;
            sa[tid]  = v ? g_perm_a[s + c0 + tid] : 0;
            ssc[tid] = v ? g_perm_score[s + c0 + tid] : 0.f;
        }
        __syncthreads();

        u64 acc[16];
#pragma unroll
        for (int r = 0; r < 16; r++)
            acc[r] = *(const u64*)(b2s + e * OW + og + 2 * r);

        for (int h0 = 0; h0 < H; h0 += 32) {
#pragma unroll
            for (int q = 0; q < 32; q++) {
                int idx = tid + 256 * q; int hh = idx >> 8, oo = idx & 255;
                ws2[hh * 258 + oo] =
                    w2s[((size_t)e * H + h0 + hh) * OW + oc * 256 + oo];
            }
#pragma unroll
            for (int q = 0; q < 4; q++) {
                int idx = tid + 256 * q; int tt = idx >> 5, hh = idx & 31;
                vst[tt * 33 + hh] =
                    (tt < nt) ? g_V[(size_t)(s + c0 + tt) * H + h0 + hh] : 0.f;
            }
            __syncthreads();
#pragma unroll 4
            for (int hh = 0; hh < 32; hh++) {
                float vv = vst[t * 33 + hh];
                u64 vp = pack2(vv, vv);
                const float* wrow = &ws2[hh * 258 + grp * 32];
#pragma unroll
                for (int r = 0; r < 16; r++) {
                    u64 wp = *(const u64*)(wrow + 2 * r);
                    ffma2(acc[r], vp, wp);
                }
            }
            __syncthreads();
        }

        if (t < nt) {
            float sc = ssc[t]; int a = sa[t];
#pragma unroll
            for (int r = 0; r < 16; r++) {
                float2 f = unpack2(acc[r]);
                float2 o; o.x = sc * f.x; o.y = sc * f.y;
                *(float2*)&g_tmp[(size_t)a * OW + og + 2 * r] = o;
            }
        }
    }
}

// ---------------- kernel 5: out[t] = tmp[t,slot0] + tmp[t,slot1] ----------------
__global__ __launch_bounds__(256) void combine_kernel(float* __restrict__ out)
{
    int idx = blockIdx.x * 256 + threadIdx.x;   // 131072 float4s
    int t = idx >> 7, o4 = idx & 127;
    const float4* tp = (const float4*)g_tmp;
    float4 a = tp[(size_t)(2 * t) * 128 + o4];
    float4 b = tp[(size_t)(2 * t + 1) * 128 + o4];
    float4 r; r.x = a.x + b.x; r.y = a.y + b.y; r.z = a.z + b.z; r.w = a.w + b.w;
    ((float4*)out)[idx] = r;
}

// ---------------- launcher ----------------
extern "C" void kernel_launch(void* const* d_in, const int* in_sizes, int n_in,
                              void* d_out, int out_size)
{
    const float* x     = (const float*)d_in[0];
    const float* noise = (const float*)d_in[1];
    const float* w1s   = (const float*)d_in[2];
    const float* b1s   = (const float*)d_in[3];
    const float* w2s   = (const float*)d_in[4];
    const float* b2s   = (const float*)d_in[5];
    const float* mixer = (const float*)d_in[6];
    const float* nctl  = (const float*)d_in[7];
    // d_in[8] = k (fixed at 2, shapes are static)

    routing_kernel<<<32, 256>>>(x, noise, mixer, nctl);
    group_kernel<<<1, 256>>>();
    ffn1_kernel<<<dim3(2, 64), 256>>>(w1s, b1s, x);
    ffn2_kernel<<<dim3(2, 64), 256>>>(w2s, b2s);
    combine_kernel<<<512, 256>>>((float*)d_out);
}

// round 3
// speedup vs baseline: 1.1525x; 1.1525x over previous
#include <cuda_runtime.h>

#define IW 512
#define H 256
#define OW 512
#define E 64
#define NA 2048

typedef unsigned long long u64;

// ---------------- device scratch (no allocs allowed) ----------------
__device__ __align__(16) float g_V[NA * H];      // 2 MB
__device__ __align__(16) float g_tmp[NA * OW];   // 4 MB
__device__ int   g_topk_idx[NA];
__device__ float g_topk_score[NA];
__device__ int   g_seg_start[E + 1];
__device__ int   g_perm_a[NA];
__device__ float g_perm_score[NA];

// ---------------- packed f32x2 helpers (sm_103a) ----------------
__device__ __forceinline__ u64 pack2(float a, float b) {
    u64 r; unsigned ai = __float_as_uint(a), bi = __float_as_uint(b);
    asm("mov.b64 %0, {%1, %2};" : "=l"(r) : "r"(ai), "r"(bi));
    return r;
}
__device__ __forceinline__ void ffma2(u64 &d, u64 a, u64 b) {
    asm("fma.rn.f32x2 %0, %1, %2, %0;" : "+l"(d) : "l"(a), "l"(b));
}
__device__ __forceinline__ float2 unpack2(u64 v) {
    unsigned lo, hi;
    asm("mov.b64 {%0, %1}, %2;" : "=r"(lo), "=r"(hi) : "l"(v));
    float2 f; f.x = __uint_as_float(lo); f.y = __uint_as_float(hi);
    return f;
}

// ---------------- kernel 1: routing ----------------
// 64 blocks x 16 tokens, 256 threads. f32x2 packs (mixer, noise_ctl) dot products.
__global__ __launch_bounds__(256) void routing_kernel(
    const float* __restrict__ x, const float* __restrict__ noise,
    const float* __restrict__ mixer, const float* __restrict__ nctl)
{
    __shared__ __align__(16) u64 mns[32][64];    // (m, n) pairs  16 KB
    __shared__ __align__(16) u64 xs2[16][32];    // (x, x) dup     4 KB
    __shared__ float hs[16][64];
    int tid = threadIdx.x;
    int t0 = blockIdx.x * 16;
    int ee = tid & 63, tg = tid >> 6;            // expert, token-group (4 tokens)

    u64 acc2[4];
#pragma unroll
    for (int j = 0; j < 4; j++) acc2[j] = 0ull;

    for (int i0 = 0; i0 < IW; i0 += 32) {
#pragma unroll
        for (int q = 0; q < 8; q++) {
            int id = tid + 256 * q; int ii = id >> 6, e2 = id & 63;
            mns[ii][e2] = pack2(mixer[(i0 + ii) * E + e2], nctl[(i0 + ii) * E + e2]);
        }
#pragma unroll
        for (int q = 0; q < 2; q++) {
            int id = tid + 256 * q; int tt = id >> 5, ii = id & 31;
            float v = x[(t0 + tt) * IW + i0 + ii];
            xs2[tt][ii] = pack2(v, v);
        }
        __syncthreads();
#pragma unroll 8
        for (int ii = 0; ii < 32; ii++) {
            u64 mn = mns[ii][ee];
#pragma unroll
            for (int j = 0; j < 4; j++)
                ffma2(acc2[j], xs2[tg * 4 + j][ii], mn);
        }
        __syncthreads();
    }

#pragma unroll
    for (int j = 0; j < 4; j++) {
        int t = tg * 4 + j;
        float2 a = unpack2(acc2[j]);            // a.x = mixer dot, a.y = nctl dot
        float z = a.y;
        float sp = (z > 20.f) ? z : log1pf(expf(z));
        hs[t][ee] = a.x + noise[(t0 + t) * E + ee] * sp;
    }
    __syncthreads();

    if (tid < 16) {
        int t = tid;
        float v0 = -1e30f, v1 = -1e30f; int i0 = -1, i1 = -1;
        for (int ec = 0; ec < 64; ec++) {
            float v = hs[t][ec];
            if (v > v0)      { v1 = v0; i1 = i0; v0 = v; i0 = ec; }
            else if (v > v1) { v1 = v; i1 = ec; }
        }
        float e1 = expf(v1 - v0);
        float s0 = 1.f / (1.f + e1);
        float s1 = e1 * s0;
        g_topk_idx[(t0 + t) * 2 + 0] = i0;
        g_topk_idx[(t0 + t) * 2 + 1] = i1;
        g_topk_score[(t0 + t) * 2 + 0] = s0;
        g_topk_score[(t0 + t) * 2 + 1] = s1;
    }
}

// ---------------- kernel 2: group assignments by expert ----------------
__global__ __launch_bounds__(256) void group_kernel()
{
    __shared__ int cnt[E];
    __shared__ int st[E + 1];
    __shared__ int cur[E];
    int tid = threadIdx.x;
    if (tid < E) cnt[tid] = 0;
    __syncthreads();
    for (int a = tid; a < NA; a += 256) atomicAdd(&cnt[g_topk_idx[a]], 1);
    __syncthreads();
    if (tid == 0) {
        int run = 0;
        for (int e2 = 0; e2 < E; e2++) { st[e2] = run; run += cnt[e2]; }
        st[E] = run;
    }
    __syncthreads();
    if (tid < E) cur[tid] = st[tid];
    if (tid <= E) g_seg_start[tid] = st[tid];
    __syncthreads();
    for (int a = tid; a < NA; a += 256) {
        int e2 = g_topk_idx[a];
        int pos = atomicAdd(&cur[e2], 1);
        g_perm_a[pos] = a;
        g_perm_score[pos] = g_topk_score[a];
    }
}

// ---------------- kernel 3: V = relu(X_e @ W1_e + b1_e) ----------------
// grid (2 h-halves, 64 experts, 8 chunk-slots), 256 threads.
// thread tile: 4 tokens x 4 h. warp = token group (broadcast x loads).
__global__ __launch_bounds__(256) void ffn1_kernel(
    const float* __restrict__ w1s, const float* __restrict__ b1s,
    const float* __restrict__ x)
{
    __shared__ __align__(16) float ws[32][132];  // [i 32][h 128 + 4 pad]
    __shared__ __align__(16) u64 xs2[32][32];    // (x,x) dup, [token][i]
    __shared__ int tok[32];
    int e = blockIdx.y, hc = blockIdx.x, z = blockIdx.z;
    int s = g_seg_start[e];
    int cnt = g_seg_start[e + 1] - s;
    int tid = threadIdx.x;
    int w = tid >> 5, l = tid & 31;
    const float* wbase = w1s + (size_t)e * IW * H + hc * 128;
    const float* bbase = b1s + e * H + hc * 128;

    for (int c0 = z * 32; c0 < cnt; c0 += 256) {
        int nt = min(32, cnt - c0);
        __syncthreads();
        if (tid < 32) tok[tid] = (tid < nt) ? (g_perm_a[s + c0 + tid] >> 1) : -1;
        __syncthreads();

        u64 acc[4][2];
        float4 bv = *(const float4*)(bbase + l * 4);
#pragma unroll
        for (int j = 0; j < 4; j++) {
            acc[j][0] = pack2(bv.x, bv.y);
            acc[j][1] = pack2(bv.z, bv.w);
        }

        for (int i0 = 0; i0 < IW; i0 += 32) {
#pragma unroll
            for (int q = 0; q < 4; q++) {
                int f4 = tid + 256 * q;           // 1024 float4s
                int row = f4 >> 5, c4 = f4 & 31;
                *(float4*)&ws[row][c4 * 4] =
                    *(const float4*)(wbase + (size_t)(i0 + row) * H + c4 * 4);
            }
#pragma unroll
            for (int q = 0; q < 4; q++) {
                int id = tid + 256 * q;           // 1024 u64s
                int tt = id >> 5, ii = id & 31;
                int tk = tok[tt];
                float v = (tk >= 0) ? x[tk * IW + i0 + ii] : 0.f;
                xs2[tt][ii] = pack2(v, v);
            }
            __syncthreads();
#pragma unroll 8
            for (int kk = 0; kk < 32; kk++) {
                ulonglong2 wl = *(ulonglong2*)&ws[kk][l * 4];
#pragma unroll
                for (int j = 0; j < 4; j++) {
                    u64 xd = xs2[w * 4 + j][kk];
                    ffma2(acc[j][0], xd, wl.x);
                    ffma2(acc[j][1], xd, wl.y);
                }
            }
            __syncthreads();
        }

#pragma unroll
        for (int j = 0; j < 4; j++) {
            int t = w * 4 + j;
            if (t < nt) {
                float2 a0 = unpack2(acc[j][0]), a1 = unpack2(acc[j][1]);
                float4 o;
                o.x = fmaxf(a0.x, 0.f); o.y = fmaxf(a0.y, 0.f);
                o.z = fmaxf(a1.x, 0.f); o.w = fmaxf(a1.y, 0.f);
                *(float4*)&g_V[(size_t)(s + c0 + t) * H + hc * 128 + l * 4] = o;
            }
        }
    }
}

// ---------------- kernel 4: tmp = score * (V_e @ W2_e + b2_e) ----------------
// grid (2 o-halves, 64 experts, 8 chunk-slots), 256 threads.
// thread tile: 4 tokens x 8 o (two 4-wide sub-tiles 128 apart -> conflict-free LDS.128).
__global__ __launch_bounds__(256) void ffn2_kernel(
    const float* __restrict__ w2s, const float* __restrict__ b2s)
{
    __shared__ __align__(16) float ws2[32][264]; // [h 32][o 256 + 8 pad]
    __shared__ __align__(16) u64 vs2[32][32];    // (v,v) dup
    int e = blockIdx.y, oc = blockIdx.x, z = blockIdx.z;
    int s = g_seg_start[e];
    int cnt = g_seg_start[e + 1] - s;
    int tid = threadIdx.x;
    int w = tid >> 5, l = tid & 31;
    const float* wbase = w2s + (size_t)e * H * OW + oc * 256;
    const float* bbase = b2s + e * OW + oc * 256;

    for (int c0 = z * 32; c0 < cnt; c0 += 256) {
        int nt = min(32, cnt - c0);
        __syncthreads();

        u64 acc[4][4];
        ulonglong2 bA = *(const ulonglong2*)(bbase + l * 4);
        ulonglong2 bB = *(const ulonglong2*)(bbase + 128 + l * 4);
#pragma unroll
        for (int j = 0; j < 4; j++) {
            acc[j][0] = bA.x; acc[j][1] = bA.y;
            acc[j][2] = bB.x; acc[j][3] = bB.y;
        }

        for (int h0 = 0; h0 < H; h0 += 32) {
#pragma unroll
            for (int q = 0; q < 8; q++) {
                int f4 = tid + 256 * q;           // 2048 float4s
                int row = f4 >> 6, c4 = f4 & 63;
                *(float4*)&ws2[row][c4 * 4] =
                    *(const float4*)(wbase + (size_t)(h0 + row) * OW + c4 * 4);
            }
#pragma unroll
            for (int q = 0; q < 4; q++) {
                int id = tid + 256 * q;           // 1024 u64s
                int tt = id >> 5, hh = id & 31;
                float v = (tt < nt) ? g_V[(size_t)(s + c0 + tt) * H + h0 + hh] : 0.f;
                vs2[tt][hh] = pack2(v, v);
            }
            __syncthreads();
#pragma unroll 4
            for (int kk = 0; kk < 32; kk++) {
                ulonglong2 wA = *(ulonglong2*)&ws2[kk][l * 4];
                ulonglong2 wB = *(ulonglong2*)&ws2[kk][128 + l * 4];
#pragma unroll
                for (int j = 0; j < 4; j++) {
                    u64 vd = vs2[w * 4 + j][kk];
                    ffma2(acc[j][0], vd, wA.x);
                    ffma2(acc[j][1], vd, wA.y);
                    ffma2(acc[j][2], vd, wB.x);
                    ffma2(acc[j][3], vd, wB.y);
                }
            }
            __syncthreads();
        }

#pragma unroll
        for (int j = 0; j < 4; j++) {
            int t = w * 4 + j;
            if (t < nt) {
                int   a  = g_perm_a[s + c0 + t];
                float sc = g_perm_score[s + c0 + t];
                float2 a0 = unpack2(acc[j][0]), a1 = unpack2(acc[j][1]);
                float2 a2 = unpack2(acc[j][2]), a3 = unpack2(acc[j][3]);
                float4 oA, oB;
                oA.x = sc * a0.x; oA.y = sc * a0.y; oA.z = sc * a1.x; oA.w = sc * a1.y;
                oB.x = sc * a2.x; oB.y = sc * a2.y; oB.z = sc * a3.x; oB.w = sc * a3.y;
                float* dst = &g_tmp[(size_t)a * OW + oc * 256 + l * 4];
                *(float4*)dst = oA;
                *(float4*)(dst + 128) = oB;
            }
        }
    }
}

// ---------------- kernel 5: out[t] = tmp[t,slot0] + tmp[t,slot1] ----------------
__global__ __launch_bounds__(256) void combine_kernel(float* __restrict__ out)
{
    int idx = blockIdx.x * 256 + threadIdx.x;   // 131072 float4s
    int t = idx >> 7, o4 = idx & 127;
    const float4* tp = (const float4*)g_tmp;
    float4 a = tp[(size_t)(2 * t) * 128 + o4];
    float4 b = tp[(size_t)(2 * t + 1) * 128 + o4];
    float4 r; r.x = a.x + b.x; r.y = a.y + b.y; r.z = a.z + b.z; r.w = a.w + b.w;
    ((float4*)out)[idx] = r;
}

// ---------------- launcher ----------------
extern "C" void kernel_launch(void* const* d_in, const int* in_sizes, int n_in,
                              void* d_out, int out_size)
{
    const float* x     = (const float*)d_in[0];
    const float* noise = (const float*)d_in[1];
    const float* w1s   = (const float*)d_in[2];
    const float* b1s   = (const float*)d_in[3];
    const float* w2s   = (const float*)d_in[4];
    const float* b2s   = (const float*)d_in[5];
    const float* mixer = (const float*)d_in[6];
    const float* nctl  = (const float*)d_in[7];

    routing_kernel<<<64, 256>>>(x, noise, mixer, nctl);
    group_kernel<<<1, 256>>>();
    ffn1_kernel<<<dim3(2, 64, 8), 256>>>(w1s, b1s, x);
    ffn2_kernel<<<dim3(2, 64, 8), 256>>>(w2s, b2s);
    combine_kernel<<<512, 256>>>((float*)d_out);
}

// round 8
// speedup vs baseline: 1.2002x; 1.0414x over previous
#include <cuda_runtime.h>

#define IW 512
#define H 256
#define OW 512
#define E 64
#define NA 2048

typedef unsigned long long u64;

// ---------------- device scratch (no allocs allowed) ----------------
__device__ __align__(16) float g_V[NA * H];      // 2 MB
__device__ int   g_topk_idx[NA];
__device__ float g_topk_score[NA];
__device__ int   g_seg_start[E + 1];
__device__ int   g_perm_a[NA];
__device__ float g_perm_score[NA];

// ---------------- packed f32x2 helpers (sm_103a) ----------------
__device__ __forceinline__ u64 pack2(float a, float b) {
    u64 r; unsigned ai = __float_as_uint(a), bi = __float_as_uint(b);
    asm("mov.b64 %0, {%1, %2};" : "=l"(r) : "r"(ai), "r"(bi));
    return r;
}
__device__ __forceinline__ void ffma2(u64 &d, u64 a, u64 b) {
    asm("fma.rn.f32x2 %0, %1, %2, %0;" : "+l"(d) : "l"(a), "l"(b));
}
__device__ __forceinline__ float2 unpack2(u64 v) {
    unsigned lo, hi;
    asm("mov.b64 {%0, %1}, %2;" : "=r"(lo), "=r"(hi) : "l"(v));
    float2 f; f.x = __uint_as_float(lo); f.y = __uint_as_float(hi);
    return f;
}

// ---------------- kernel 0: zero the output (d_out poisoned 0xAA) ----------------
__global__ __launch_bounds__(256) void zero_kernel(float4* __restrict__ out)
{
    int idx = blockIdx.x * 256 + threadIdx.x;   // 131072 float4s
    out[idx] = make_float4(0.f, 0.f, 0.f, 0.f);
}

// ---------------- kernel 1: routing ----------------
// 128 blocks x 8 tokens, 256 threads. f32x2 packs (mixer, noise_ctl) dots.
__global__ __launch_bounds__(256) void routing_kernel(
    const float* __restrict__ x, const float* __restrict__ noise,
    const float* __restrict__ mixer, const float* __restrict__ nctl)
{
    __shared__ __align__(16) u64 mns[32][64];    // (m, n) pairs 16 KB
    __shared__ __align__(16) u64 xs2[8][32];     // (x, x) dup    2 KB
    __shared__ float hs[8][64];
    int tid = threadIdx.x;
    int t0 = blockIdx.x * 8;
    int ee = tid & 63, tg = tid >> 6;            // expert, token-group (2 tokens)

    u64 acc2[2] = {0ull, 0ull};

    for (int i0 = 0; i0 < IW; i0 += 32) {
#pragma unroll
        for (int q = 0; q < 8; q++) {
            int id = tid + 256 * q; int ii = id >> 6, e2 = id & 63;
            mns[ii][e2] = pack2(mixer[(i0 + ii) * E + e2], nctl[(i0 + ii) * E + e2]);
        }
        if (tid < 256) {
            int tt = tid >> 5, ii = tid & 31;
            if (tt < 8) {
                float v = x[(t0 + tt) * IW + i0 + ii];
                xs2[tt][ii] = pack2(v, v);
            }
        }
        __syncthreads();
#pragma unroll 8
        for (int ii = 0; ii < 32; ii++) {
            u64 mn = mns[ii][ee];
            ffma2(acc2[0], xs2[tg * 2 + 0][ii], mn);
            ffma2(acc2[1], xs2[tg * 2 + 1][ii], mn);
        }
        __syncthreads();
    }

#pragma unroll
    for (int j = 0; j < 2; j++) {
        int t = tg * 2 + j;
        float2 a = unpack2(acc2[j]);
        float z = a.y;
        float sp = (z > 20.f) ? z : log1pf(expf(z));
        hs[t][ee] = a.x + noise[(t0 + t) * E + ee] * sp;
    }
    __syncthreads();

    if (tid < 8) {
        int t = tid;
        float v0 = -1e30f, v1 = -1e30f; int i0 = -1, i1 = -1;
        for (int ec = 0; ec < 64; ec++) {
            float v = hs[t][ec];
            if (v > v0)      { v1 = v0; i1 = i0; v0 = v; i0 = ec; }
            else if (v > v1) { v1 = v; i1 = ec; }
        }
        float e1 = expf(v1 - v0);
        float s0 = 1.f / (1.f + e1);
        float s1 = e1 * s0;
        g_topk_idx[(t0 + t) * 2 + 0] = i0;
        g_topk_idx[(t0 + t) * 2 + 1] = i1;
        g_topk_score[(t0 + t) * 2 + 0] = s0;
        g_topk_score[(t0 + t) * 2 + 1] = s1;
    }
}

// ---------------- kernel 2: group assignments by expert ----------------
__global__ __launch_bounds__(256) void group_kernel()
{
    __shared__ int cnt[E];
    __shared__ int st[E + 1];
    __shared__ int cur[E];
    int tid = threadIdx.x;
    if (tid < E) cnt[tid] = 0;
    __syncthreads();
    for (int a = tid; a < NA; a += 256) atomicAdd(&cnt[g_topk_idx[a]], 1);
    __syncthreads();
    if (tid == 0) {
        int run = 0;
        for (int e2 = 0; e2 < E; e2++) { st[e2] = run; run += cnt[e2]; }
        st[E] = run;
    }
    __syncthreads();
    if (tid < E) cur[tid] = st[tid];
    if (tid <= E) g_seg_start[tid] = st[tid];
    __syncthreads();
    for (int a = tid; a < NA; a += 256) {
        int e2 = g_topk_idx[a];
        int pos = atomicAdd(&cur[e2], 1);
        g_perm_a[pos] = a;
        g_perm_score[pos] = g_topk_score[a];
    }
}

// ---------------- kernel 3: V = relu(X_e @ W1_e + b1_e) ----------------
// grid (2 h-halves, 64 experts, 8 chunk-slots), 256 thr, chunk = 16 tokens.
// per-thread tile: 2 tokens x 4 h. Register double-buffered gmem->smem.
__global__ __launch_bounds__(256) void ffn1_kernel(
    const float* __restrict__ w1s, const float* __restrict__ b1s,
    const float* __restrict__ x)
{
    __shared__ __align__(16) float ws[32][132];  // [i 32][h 128 + 4 pad] 16.9 KB
    __shared__ __align__(16) u64 xs2[16][32];    // (x,x) dup [tok][i]     4 KB
    __shared__ int tok[16];
    int e = blockIdx.y, hc = blockIdx.x, z = blockIdx.z;
    int s = g_seg_start[e];
    int cnt = g_seg_start[e + 1] - s;
    int tid = threadIdx.x;
    int w = tid >> 5, l = tid & 31;
    const float* wbase = w1s + (size_t)e * IW * H + hc * 128;
    const float* bbase = b1s + e * H + hc * 128;

    // addressing for cooperative tile loads
    int wr0 = (tid + 0)   >> 5, wc0 = ((tid + 0)   & 31) * 4;
    int wr1 = (tid + 256) >> 5, wc1 = ((tid + 256) & 31) * 4;
    int wr2 = (tid + 512) >> 5, wc2 = ((tid + 512) & 31) * 4;
    int wr3 = (tid + 768) >> 5, wc3 = ((tid + 768) & 31) * 4;
    int xt0 = tid >> 5,        xi0 = tid & 31;          // token 0..7
    int xt1 = (tid + 256) >> 5, xi1 = (tid + 256) & 31; // token 8..15

    for (int c0 = z * 16; c0 < cnt; c0 += 128) {
        int nt = min(16, cnt - c0);
        __syncthreads();
        if (tid < 16) tok[tid] = (tid < nt) ? (g_perm_a[s + c0 + tid] >> 1) : -1;
        __syncthreads();

        float4 pw0, pw1, pw2, pw3; float px0, px1;
        {   // prologue prefetch: tile i0 = 0
            pw0 = *(const float4*)(wbase + (size_t)wr0 * H + wc0);
            pw1 = *(const float4*)(wbase + (size_t)wr1 * H + wc1);
            pw2 = *(const float4*)(wbase + (size_t)wr2 * H + wc2);
            pw3 = *(const float4*)(wbase + (size_t)wr3 * H + wc3);
            int k0 = tok[xt0], k1 = tok[xt1];
            px0 = (k0 >= 0) ? x[k0 * IW + xi0] : 0.f;
            px1 = (k1 >= 0) ? x[k1 * IW + xi1] : 0.f;
        }

        u64 acc[2][2];
        float4 bv = *(const float4*)(bbase + l * 4);
        acc[0][0] = pack2(bv.x, bv.y); acc[0][1] = pack2(bv.z, bv.w);
        acc[1][0] = acc[0][0];         acc[1][1] = acc[0][1];

        for (int i0 = 0; i0 < IW; i0 += 32) {
            // commit prefetched tile to smem
            *(float4*)&ws[wr0][wc0] = pw0;
            *(float4*)&ws[wr1][wc1] = pw1;
            *(float4*)&ws[wr2][wc2] = pw2;
            *(float4*)&ws[wr3][wc3] = pw3;
            xs2[xt0][xi0] = pack2(px0, px0);
            xs2[xt1][xi1] = pack2(px1, px1);
            __syncthreads();

            if (i0 + 32 < IW) {   // prefetch next tile while computing
                const float* wb = wbase + (size_t)(i0 + 32) * H;
                pw0 = *(const float4*)(wb + (size_t)wr0 * H + wc0);
                pw1 = *(const float4*)(wb + (size_t)wr1 * H + wc1);
                pw2 = *(const float4*)(wb + (size_t)wr2 * H + wc2);
                pw3 = *(const float4*)(wb + (size_t)wr3 * H + wc3);
                int k0 = tok[xt0], k1 = tok[xt1];
                px0 = (k0 >= 0) ? x[k0 * IW + i0 + 32 + xi0] : 0.f;
                px1 = (k1 >= 0) ? x[k1 * IW + i0 + 32 + xi1] : 0.f;
            }
#pragma unroll 8
            for (int kk = 0; kk < 32; kk++) {
                ulonglong2 wl = *(ulonglong2*)&ws[kk][l * 4];
                u64 x0 = xs2[w * 2 + 0][kk];
                u64 x1 = xs2[w * 2 + 1][kk];
                ffma2(acc[0][0], x0, wl.x);
                ffma2(acc[0][1], x0, wl.y);
                ffma2(acc[1][0], x1, wl.x);
                ffma2(acc[1][1], x1, wl.y);
            }
            __syncthreads();
        }

#pragma unroll
        for (int j = 0; j < 2; j++) {
            int t = w * 2 + j;
            if (t < nt) {
                float2 a0 = unpack2(acc[j][0]), a1 = unpack2(acc[j][1]);
                float4 o;
                o.x = fmaxf(a0.x, 0.f); o.y = fmaxf(a0.y, 0.f);
                o.z = fmaxf(a1.x, 0.f); o.w = fmaxf(a1.y, 0.f);
                *(float4*)&g_V[(size_t)(s + c0 + t) * H + hc * 128 + l * 4] = o;
            }
        }
    }
}

// ---------------- kernel 4: out += score * (V_e @ W2_e + b2_e) ----------------
// grid (2 o-halves, 64 experts, 8 chunk-slots), 256 thr, chunk = 16 tokens.
// per-thread tile: 2 tokens x 8 o. Atomic scatter-add into d_out (2 commutative
// adds per element -> deterministic). Register double-buffered.
__global__ __launch_bounds__(256) void ffn2_kernel(
    const float* __restrict__ w2s, const float* __restrict__ b2s,
    float* __restrict__ out)
{
    __shared__ __align__(16) float ws2[32][264]; // [h 32][o 256 + 8 pad] 33.8 KB
    __shared__ __align__(16) u64 vs2[16][32];    // (v,v) dup              4 KB
    int e = blockIdx.y, oc = blockIdx.x, z = blockIdx.z;
    int s = g_seg_start[e];
    int cnt = g_seg_start[e + 1] - s;
    int tid = threadIdx.x;
    int w = tid >> 5, l = tid & 31;
    const float* wbase = w2s + (size_t)e * H * OW + oc * 256;
    const float* bbase = b2s + e * OW + oc * 256;

    int wrr[8], wcc[8];
#pragma unroll
    for (int q = 0; q < 8; q++) {
        int f4 = tid + 256 * q;
        wrr[q] = f4 >> 6; wcc[q] = (f4 & 63) * 4;
    }
    int vt0 = tid >> 5,        vh0 = tid & 31;
    int vt1 = (tid + 256) >> 5, vh1 = (tid + 256) & 31;

    for (int c0 = z * 16; c0 < cnt; c0 += 128) {
        int nt = min(16, cnt - c0);
        __syncthreads();

        float4 pw[8]; float pv0, pv1;
        {   // prologue prefetch: tile h0 = 0
#pragma unroll
            for (int q = 0; q < 8; q++)
                pw[q] = *(const float4*)(wbase + (size_t)wrr[q] * OW + wcc[q]);
            pv0 = (vt0 < nt) ? g_V[(size_t)(s + c0 + vt0) * H + vh0] : 0.f;
            pv1 = (vt1 < nt) ? g_V[(size_t)(s + c0 + vt1) * H + vh1] : 0.f;
        }

        u64 acc[2][4];
        ulonglong2 bA = *(const ulonglong2*)(bbase + l * 4);
        ulonglong2 bB = *(const ulonglong2*)(bbase + 128 + l * 4);
        acc[0][0] = bA.x; acc[0][1] = bA.y; acc[0][2] = bB.x; acc[0][3] = bB.y;
        acc[1][0] = bA.x; acc[1][1] = bA.y; acc[1][2] = bB.x; acc[1][3] = bB.y;

        for (int h0 = 0; h0 < H; h0 += 32) {
#pragma unroll
            for (int q = 0; q < 8; q++)
                *(float4*)&ws2[wrr[q]][wcc[q]] = pw[q];
            vs2[vt0][vh0] = pack2(pv0, pv0);
            vs2[vt1][vh1] = pack2(pv1, pv1);
            __syncthreads();

            if (h0 + 32 < H) {
                const float* wb = wbase + (size_t)(h0 + 32) * OW;
#pragma unroll
                for (int q = 0; q < 8; q++)
                    pw[q] = *(const float4*)(wb + (size_t)wrr[q] * OW + wcc[q]);
                pv0 = (vt0 < nt) ? g_V[(size_t)(s + c0 + vt0) * H + h0 + 32 + vh0] : 0.f;
                pv1 = (vt1 < nt) ? g_V[(size_t)(s + c0 + vt1) * H + h0 + 32 + vh1] : 0.f;
            }
#pragma unroll 4
            for (int kk = 0; kk < 32; kk++) {
                ulonglong2 wA = *(ulonglong2*)&ws2[kk][l * 4];
                ulonglong2 wB = *(ulonglong2*)&ws2[kk][128 + l * 4];
                u64 v0 = vs2[w * 2 + 0][kk];
                u64 v1 = vs2[w * 2 + 1][kk];
                ffma2(acc[0][0], v0, wA.x);
                ffma2(acc[0][1], v0, wA.y);
                ffma2(acc[0][2], v0, wB.x);
                ffma2(acc[0][3], v0, wB.y);
                ffma2(acc[1][0], v1, wA.x);
                ffma2(acc[1][1], v1, wA.y);
                ffma2(acc[1][2], v1, wB.x);
                ffma2(acc[1][3], v1, wB.y);
            }
            __syncthreads();
        }

#pragma unroll
        for (int j = 0; j < 2; j++) {
            int t = w * 2 + j;
            if (t < nt) {
                int   a  = g_perm_a[s + c0 + t];
                float sc = g_perm_score[s + c0 + t];
                int   tk = a >> 1;
                float* dst = out + (size_t)tk * OW + oc * 256 + l * 4;
#pragma unroll
                for (int r = 0; r < 4; r++) {
                    float2 f = unpack2(acc[j][r]);
                    int off = (r >> 1) * 128 + (r & 1) * 2;
                    atomicAdd(dst + off,     sc * f.x);
                    atomicAdd(dst + off + 1, sc * f.y);
                }
            }
        }
    }
}

// ---------------- launcher ----------------
extern "C" void kernel_launch(void* const* d_in, const int* in_sizes, int n_in,
                              void* d_out, int out_size)
{
    const float* x     = (const float*)d_in[0];
    const float* noise = (const float*)d_in[1];
    const float* w1s   = (const float*)d_in[2];
    const float* b1s   = (const float*)d_in[3];
    const float* w2s   = (const float*)d_in[4];
    const float* b2s   = (const float*)d_in[5];
    const float* mixer = (const float*)d_in[6];
    const float* nctl  = (const float*)d_in[7];

    zero_kernel<<<512, 256>>>((float4*)d_out);
    routing_kernel<<<128, 256>>>(x, noise, mixer, nctl);
    group_kernel<<<1, 256>>>();
    ffn1_kernel<<<dim3(2, 64, 8), 256>>>(w1s, b1s, x);
    ffn2_kernel<<<dim3(2, 64, 8), 256>>>(w2s, b2s, (float*)d_out);
}

// round 9
// speedup vs baseline: 1.3668x; 1.1388x over previous
#include <cuda_runtime.h>

#define IW 512
#define H 256
#define OW 512
#define E 64
#define NA 2048

typedef unsigned long long u64;

// ---------------- device scratch (no allocs allowed) ----------------
__device__ __align__(16) float g_V[NA * H];      // 2 MB
__device__ int   g_topk_idx[NA];
__device__ float g_topk_score[NA];
__device__ int   g_seg_start[E + 1];
__device__ int   g_perm_a[NA];
__device__ float g_perm_score[NA];

// ---------------- packed f32x2 helpers (sm_103a) ----------------
__device__ __forceinline__ u64 pack2(float a, float b) {
    u64 r; unsigned ai = __float_as_uint(a), bi = __float_as_uint(b);
    asm("mov.b64 %0, {%1, %2};" : "=l"(r) : "r"(ai), "r"(bi));
    return r;
}
__device__ __forceinline__ void ffma2(u64 &d, u64 a, u64 b) {
    asm("fma.rn.f32x2 %0, %1, %2, %0;" : "+l"(d) : "l"(a), "l"(b));
}
__device__ __forceinline__ float2 unpack2(u64 v) {
    unsigned lo, hi;
    asm("mov.b64 {%0, %1}, %2;" : "=r"(lo), "=r"(hi) : "l"(v));
    float2 f; f.x = __uint_as_float(lo); f.y = __uint_as_float(hi);
    return f;
}

// ---------------- kernel 0: zero the output ----------------
__global__ __launch_bounds__(256) void zero_kernel(float4* __restrict__ out)
{
    int idx = blockIdx.x * 256 + threadIdx.x;
    out[idx] = make_float4(0.f, 0.f, 0.f, 0.f);
}

// ---------------- kernel 1: routing ----------------
__global__ __launch_bounds__(256) void routing_kernel(
    const float* __restrict__ x, const float* __restrict__ noise,
    const float* __restrict__ mixer, const float* __restrict__ nctl)
{
    __shared__ __align__(16) u64 mns[32][64];
    __shared__ __align__(16) u64 xs2[8][32];
    __shared__ float hs[8][64];
    int tid = threadIdx.x;
    int t0 = blockIdx.x * 8;
    int ee = tid & 63, tg = tid >> 6;

    u64 acc2[2] = {0ull, 0ull};

    for (int i0 = 0; i0 < IW; i0 += 32) {
#pragma unroll
        for (int q = 0; q < 8; q++) {
            int id = tid + 256 * q; int ii = id >> 6, e2 = id & 63;
            mns[ii][e2] = pack2(mixer[(i0 + ii) * E + e2], nctl[(i0 + ii) * E + e2]);
        }
        {
            int tt = tid >> 5, ii = tid & 31;
            if (tt < 8) {
                float v = x[(t0 + tt) * IW + i0 + ii];
                xs2[tt][ii] = pack2(v, v);
            }
        }
        __syncthreads();
#pragma unroll 8
        for (int ii = 0; ii < 32; ii++) {
            u64 mn = mns[ii][ee];
            ffma2(acc2[0], xs2[tg * 2 + 0][ii], mn);
            ffma2(acc2[1], xs2[tg * 2 + 1][ii], mn);
        }
        __syncthreads();
    }

#pragma unroll
    for (int j = 0; j < 2; j++) {
        int t = tg * 2 + j;
        float2 a = unpack2(acc2[j]);
        float z = a.y;
        float sp = (z > 20.f) ? z : log1pf(expf(z));
        hs[t][ee] = a.x + noise[(t0 + t) * E + ee] * sp;
    }
    __syncthreads();

    if (tid < 8) {
        int t = tid;
        float v0 = -1e30f, v1 = -1e30f; int i0 = -1, i1 = -1;
        for (int ec = 0; ec < 64; ec++) {
            float v = hs[t][ec];
            if (v > v0)      { v1 = v0; i1 = i0; v0 = v; i0 = ec; }
            else if (v > v1) { v1 = v; i1 = ec; }
        }
        float e1 = expf(v1 - v0);
        float s0 = 1.f / (1.f + e1);
        float s1 = e1 * s0;
        g_topk_idx[(t0 + t) * 2 + 0] = i0;
        g_topk_idx[(t0 + t) * 2 + 1] = i1;
        g_topk_score[(t0 + t) * 2 + 0] = s0;
        g_topk_score[(t0 + t) * 2 + 1] = s1;
    }
}

// ---------------- kernel 2: group assignments by expert ----------------
__global__ __launch_bounds__(256) void group_kernel()
{
    __shared__ int cnt[E];
    __shared__ int st[E + 1];
    __shared__ int cur[E];
    int tid = threadIdx.x;
    if (tid < E) cnt[tid] = 0;
    __syncthreads();
    for (int a = tid; a < NA; a += 256) atomicAdd(&cnt[g_topk_idx[a]], 1);
    __syncthreads();
    if (tid == 0) {
        int run = 0;
        for (int e2 = 0; e2 < E; e2++) { st[e2] = run; run += cnt[e2]; }
        st[E] = run;
    }
    __syncthreads();
    if (tid < E) cur[tid] = st[tid];
    if (tid <= E) g_seg_start[tid] = st[tid];
    __syncthreads();
    for (int a = tid; a < NA; a += 256) {
        int e2 = g_topk_idx[a];
        int pos = atomicAdd(&cur[e2], 1);
        g_perm_a[pos] = a;
        g_perm_score[pos] = g_topk_score[a];
    }
}

// ---------------- kernel 3: V = relu(X_e @ W1_e + b1_e) ----------------
// grid (2 hc, 64 e, 4 z), 256 thr, chunk = 32 tokens, 4 tok/warp x 4 h/lane.
// x lives in registers, broadcast via shfl. smem holds only weights.
__global__ __launch_bounds__(256, 2) void ffn1_kernel(
    const float* __restrict__ w1s, const float* __restrict__ b1s,
    const float* __restrict__ x)
{
    __shared__ __align__(16) float ws[32][132];  // [i 32][h 128 + 4 pad] 16.9 KB
    __shared__ int tok[32];
    int e = blockIdx.y, hc = blockIdx.x, z = blockIdx.z;
    int s = g_seg_start[e];
    int cnt = g_seg_start[e + 1] - s;
    int tid = threadIdx.x;
    int w = tid >> 5, l = tid & 31;
    const float* wbase = w1s + (size_t)e * IW * H + hc * 128;

    int wr[4], wc[4];
#pragma unroll
    for (int q = 0; q < 4; q++) {
        int f4 = tid + 256 * q;
        wr[q] = f4 >> 5; wc[q] = (f4 & 31) * 4;
    }

    for (int c0 = z * 32; c0 < cnt; c0 += 128) {
        int nt = min(32, cnt - c0);
        __syncthreads();
        if (tid < 32) tok[tid] = (tid < nt) ? (g_perm_a[s + c0 + tid] >> 1) : -1;
        __syncthreads();
        int tk0 = tok[w * 4 + 0], tk1 = tok[w * 4 + 1];
        int tk2 = tok[w * 4 + 2], tk3 = tok[w * 4 + 3];

        // prologue prefetch: tile i0 = 0
        float4 pw[4];
#pragma unroll
        for (int q = 0; q < 4; q++)
            pw[q] = *(const float4*)(wbase + (size_t)wr[q] * H + wc[q]);
        float px0 = (tk0 >= 0) ? x[tk0 * IW + l] : 0.f;
        float px1 = (tk1 >= 0) ? x[tk1 * IW + l] : 0.f;
        float px2 = (tk2 >= 0) ? x[tk2 * IW + l] : 0.f;
        float px3 = (tk3 >= 0) ? x[tk3 * IW + l] : 0.f;

        u64 acc[4][2];
        float4 bv = *(const float4*)(b1s + e * H + hc * 128 + l * 4);
#pragma unroll
        for (int j = 0; j < 4; j++) {
            acc[j][0] = pack2(bv.x, bv.y);
            acc[j][1] = pack2(bv.z, bv.w);
        }

        for (int i0 = 0; i0 < IW; i0 += 32) {
#pragma unroll
            for (int q = 0; q < 4; q++)
                *(float4*)&ws[wr[q]][wc[q]] = pw[q];
            float xr0 = px0, xr1 = px1, xr2 = px2, xr3 = px3;
            __syncthreads();

            if (i0 + 32 < IW) {
                const float* wb = wbase + (size_t)(i0 + 32) * H;
#pragma unroll
                for (int q = 0; q < 4; q++)
                    pw[q] = *(const float4*)(wb + (size_t)wr[q] * H + wc[q]);
                int ib = i0 + 32 + l;
                px0 = (tk0 >= 0) ? x[tk0 * IW + ib] : 0.f;
                px1 = (tk1 >= 0) ? x[tk1 * IW + ib] : 0.f;
                px2 = (tk2 >= 0) ? x[tk2 * IW + ib] : 0.f;
                px3 = (tk3 >= 0) ? x[tk3 * IW + ib] : 0.f;
            }
#pragma unroll
            for (int kk = 0; kk < 32; kk++) {
                ulonglong2 wl = *(ulonglong2*)&ws[kk][l * 4];
                float s0 = __shfl_sync(0xffffffffu, xr0, kk);
                float s1 = __shfl_sync(0xffffffffu, xr1, kk);
                float s2 = __shfl_sync(0xffffffffu, xr2, kk);
                float s3 = __shfl_sync(0xffffffffu, xr3, kk);
                u64 d0 = pack2(s0, s0), d1 = pack2(s1, s1);
                u64 d2 = pack2(s2, s2), d3 = pack2(s3, s3);
                ffma2(acc[0][0], d0, wl.x); ffma2(acc[0][1], d0, wl.y);
                ffma2(acc[1][0], d1, wl.x); ffma2(acc[1][1], d1, wl.y);
                ffma2(acc[2][0], d2, wl.x); ffma2(acc[2][1], d2, wl.y);
                ffma2(acc[3][0], d3, wl.x); ffma2(acc[3][1], d3, wl.y);
            }
            __syncthreads();
        }

#pragma unroll
        for (int j = 0; j < 4; j++) {
            int t = w * 4 + j;
            if (t < nt) {
                float2 a0 = unpack2(acc[j][0]), a1 = unpack2(acc[j][1]);
                float4 o;
                o.x = fmaxf(a0.x, 0.f); o.y = fmaxf(a0.y, 0.f);
                o.z = fmaxf(a1.x, 0.f); o.w = fmaxf(a1.y, 0.f);
                *(float4*)&g_V[(size_t)(s + c0 + t) * H + hc * 128 + l * 4] = o;
            }
        }
    }
}

// ---------------- kernel 4: out += score * (V_e @ W2_e + b2_e) ----------------
// grid (2 oc, 64 e, 4 z), 256 thr, chunk = 32 tokens, 4 tok/warp x 8 o/lane.
// V in registers via shfl; atomic scatter-add epilogue (2 adds/elem, deterministic).
__global__ __launch_bounds__(256, 2) void ffn2_kernel(
    const float* __restrict__ w2s, const float* __restrict__ b2s,
    float* __restrict__ out)
{
    __shared__ __align__(16) float ws2[32][264]; // [h 32][o 256 + 8 pad] 33.8 KB
    int e = blockIdx.y, oc = blockIdx.x, z = blockIdx.z;
    int s = g_seg_start[e];
    int cnt = g_seg_start[e + 1] - s;
    int tid = threadIdx.x;
    int w = tid >> 5, l = tid & 31;
    const float* wbase = w2s + (size_t)e * H * OW + oc * 256;
    const float* bbase = b2s + e * OW + oc * 256;

    int wr[8], wc[8];
#pragma unroll
    for (int q = 0; q < 8; q++) {
        int f4 = tid + 256 * q;
        wr[q] = f4 >> 6; wc[q] = (f4 & 63) * 4;
    }

    for (int c0 = z * 32; c0 < cnt; c0 += 128) {
        int nt = min(32, cnt - c0);
        int r0 = w * 4 + 0, r1 = w * 4 + 1, r2 = w * 4 + 2, r3 = w * 4 + 3;
        __syncthreads();

        // prologue prefetch: tile h0 = 0
        float4 pw[8];
#pragma unroll
        for (int q = 0; q < 8; q++)
            pw[q] = *(const float4*)(wbase + (size_t)wr[q] * OW + wc[q]);
        float pv0 = (r0 < nt) ? g_V[(size_t)(s + c0 + r0) * H + l] : 0.f;
        float pv1 = (r1 < nt) ? g_V[(size_t)(s + c0 + r1) * H + l] : 0.f;
        float pv2 = (r2 < nt) ? g_V[(size_t)(s + c0 + r2) * H + l] : 0.f;
        float pv3 = (r3 < nt) ? g_V[(size_t)(s + c0 + r3) * H + l] : 0.f;

        u64 acc[4][4];
        ulonglong2 bA = *(const ulonglong2*)(bbase + l * 4);
        ulonglong2 bB = *(const ulonglong2*)(bbase + 128 + l * 4);
#pragma unroll
        for (int j = 0; j < 4; j++) {
            acc[j][0] = bA.x; acc[j][1] = bA.y;
            acc[j][2] = bB.x; acc[j][3] = bB.y;
        }

        for (int h0 = 0; h0 < H; h0 += 32) {
#pragma unroll
            for (int q = 0; q < 8; q++)
                *(float4*)&ws2[wr[q]][wc[q]] = pw[q];
            float vr0 = pv0, vr1 = pv1, vr2 = pv2, vr3 = pv3;
            __syncthreads();

            if (h0 + 32 < H) {
                const float* wb = wbase + (size_t)(h0 + 32) * OW;
#pragma unroll
                for (int q = 0; q < 8; q++)
                    pw[q] = *(const float4*)(wb + (size_t)wr[q] * OW + wc[q]);
                int hb = h0 + 32 + l;
                pv0 = (r0 < nt) ? g_V[(size_t)(s + c0 + r0) * H + hb] : 0.f;
                pv1 = (r1 < nt) ? g_V[(size_t)(s + c0 + r1) * H + hb] : 0.f;
                pv2 = (r2 < nt) ? g_V[(size_t)(s + c0 + r2) * H + hb] : 0.f;
                pv3 = (r3 < nt) ? g_V[(size_t)(s + c0 + r3) * H + hb] : 0.f;
            }
#pragma unroll
            for (int kk = 0; kk < 32; kk++) {
                ulonglong2 wA = *(ulonglong2*)&ws2[kk][l * 4];
                ulonglong2 wB = *(ulonglong2*)&ws2[kk][128 + l * 4];
                float s0 = __shfl_sync(0xffffffffu, vr0, kk);
                float s1 = __shfl_sync(0xffffffffu, vr1, kk);
                float s2 = __shfl_sync(0xffffffffu, vr2, kk);
                float s3 = __shfl_sync(0xffffffffu, vr3, kk);
                u64 d0 = pack2(s0, s0), d1 = pack2(s1, s1);
                u64 d2 = pack2(s2, s2), d3 = pack2(s3, s3);
                ffma2(acc[0][0], d0, wA.x); ffma2(acc[0][1], d0, wA.y);
                ffma2(acc[0][2], d0, wB.x); ffma2(acc[0][3], d0, wB.y);
                ffma2(acc[1][0], d1, wA.x); ffma2(acc[1][1], d1, wA.y);
                ffma2(acc[1][2], d1, wB.x); ffma2(acc[1][3], d1, wB.y);
                ffma2(acc[2][0], d2, wA.x); ffma2(acc[2][1], d2, wA.y);
                ffma2(acc[2][2], d2, wB.x); ffma2(acc[2][3], d2, wB.y);
                ffma2(acc[3][0], d3, wA.x); ffma2(acc[3][1], d3, wA.y);
                ffma2(acc[3][2], d3, wB.x); ffma2(acc[3][3], d3, wB.y);
            }
            __syncthreads();
        }

#pragma unroll
        for (int j = 0; j < 4; j++) {
            int t = w * 4 + j;
            if (t < nt) {
                int   a  = g_perm_a[s + c0 + t];
                float sc = g_perm_score[s + c0 + t];
                int   tk = a >> 1;
                float* dst = out + (size_t)tk * OW + oc * 256 + l * 4;
#pragma unroll
                for (int r = 0; r < 4; r++) {
                    float2 f = unpack2(acc[j][r]);
                    int off = (r >> 1) * 128 + (r & 1) * 2;
                    atomicAdd(dst + off,     sc * f.x);
                    atomicAdd(dst + off + 1, sc * f.y);
                }
            }
        }
    }
}

// ---------------- launcher ----------------
extern "C" void kernel_launch(void* const* d_in, const int* in_sizes, int n_in,
                              void* d_out, int out_size)
{
    const float* x     = (const float*)d_in[0];
    const float* noise = (const float*)d_in[1];
    const float* w1s   = (const float*)d_in[2];
    const float* b1s   = (const float*)d_in[3];
    const float* w2s   = (const float*)d_in[4];
    const float* b2s   = (const float*)d_in[5];
    const float* mixer = (const float*)d_in[6];
    const float* nctl  = (const float*)d_in[7];

    zero_kernel<<<512, 256>>>((float4*)d_out);
    routing_kernel<<<128, 256>>>(x, noise, mixer, nctl);
    group_kernel<<<1, 256>>>();
    ffn1_kernel<<<dim3(2, 64, 4), 256>>>(w1s, b1s, x);
    ffn2_kernel<<<dim3(2, 64, 4), 256>>>(w2s, b2s, (float*)d_out);
}

// round 10
// speedup vs baseline: 1.3692x; 1.0018x over previous
#include <cuda_runtime.h>

#define IW 512
#define H 256
#define OW 512
#define E 64
#define NA 2048

typedef unsigned long long u64;

// ---------------- device scratch (no allocs allowed) ----------------
__device__ __align__(16) float g_V[NA * H];      // 2 MB
__device__ int   g_topk_idx[NA];
__device__ float g_topk_score[NA];
__device__ int   g_seg_start[E + 1];
__device__ int   g_perm_a[NA];
__device__ float g_perm_score[NA];

// ---------------- packed f32x2 helpers (sm_103a) ----------------
__device__ __forceinline__ u64 pack2(float a, float b) {
    u64 r; unsigned ai = __float_as_uint(a), bi = __float_as_uint(b);
    asm("mov.b64 %0, {%1, %2};" : "=l"(r) : "r"(ai), "r"(bi));
    return r;
}
__device__ __forceinline__ void ffma2(u64 &d, u64 a, u64 b) {
    asm("fma.rn.f32x2 %0, %1, %2, %0;" : "+l"(d) : "l"(a), "l"(b));
}
__device__ __forceinline__ float2 unpack2(u64 v) {
    unsigned lo, hi;
    asm("mov.b64 {%0, %1}, %2;" : "=r"(lo), "=r"(hi) : "l"(v));
    float2 f; f.x = __uint_as_float(lo); f.y = __uint_as_float(hi);
    return f;
}

// ---------------- kernel 0: zero the output ----------------
__global__ __launch_bounds__(256) void zero_kernel(float4* __restrict__ out)
{
    int idx = blockIdx.x * 256 + threadIdx.x;
    out[idx] = make_float4(0.f, 0.f, 0.f, 0.f);
}

// ---------------- kernel 1: routing ----------------
__global__ __launch_bounds__(256) void routing_kernel(
    const float* __restrict__ x, const float* __restrict__ noise,
    const float* __restrict__ mixer, const float* __restrict__ nctl)
{
    __shared__ __align__(16) u64 mns[32][64];
    __shared__ __align__(16) u64 xs2[8][32];
    __shared__ float hs[8][64];
    int tid = threadIdx.x;
    int t0 = blockIdx.x * 8;
    int ee = tid & 63, tg = tid >> 6;

    u64 acc2[2] = {0ull, 0ull};

    for (int i0 = 0; i0 < IW; i0 += 32) {
#pragma unroll
        for (int q = 0; q < 8; q++) {
            int id = tid + 256 * q; int ii = id >> 6, e2 = id & 63;
            mns[ii][e2] = pack2(mixer[(i0 + ii) * E + e2], nctl[(i0 + ii) * E + e2]);
        }
        {
            int tt = tid >> 5, ii = tid & 31;
            if (tt < 8) {
                float v = x[(t0 + tt) * IW + i0 + ii];
                xs2[tt][ii] = pack2(v, v);
            }
        }
        __syncthreads();
#pragma unroll 8
        for (int ii = 0; ii < 32; ii++) {
            u64 mn = mns[ii][ee];
            ffma2(acc2[0], xs2[tg * 2 + 0][ii], mn);
            ffma2(acc2[1], xs2[tg * 2 + 1][ii], mn);
        }
        __syncthreads();
    }

#pragma unroll
    for (int j = 0; j < 2; j++) {
        int t = tg * 2 + j;
        float2 a = unpack2(acc2[j]);
        float z = a.y;
        float sp = (z > 20.f) ? z : log1pf(expf(z));
        hs[t][ee] = a.x + noise[(t0 + t) * E + ee] * sp;
    }
    __syncthreads();

    if (tid < 8) {
        int t = tid;
        float v0 = -1e30f, v1 = -1e30f; int i0 = -1, i1 = -1;
        for (int ec = 0; ec < 64; ec++) {
            float v = hs[t][ec];
            if (v > v0)      { v1 = v0; i1 = i0; v0 = v; i0 = ec; }
            else if (v > v1) { v1 = v; i1 = ec; }
        }
        float e1 = expf(v1 - v0);
        float s0 = 1.f / (1.f + e1);
        float s1 = e1 * s0;
        g_topk_idx[(t0 + t) * 2 + 0] = i0;
        g_topk_idx[(t0 + t) * 2 + 1] = i1;
        g_topk_score[(t0 + t) * 2 + 0] = s0;
        g_topk_score[(t0 + t) * 2 + 1] = s1;
    }
}

// ---------------- kernel 2: group assignments by expert ----------------
__global__ __launch_bounds__(256) void group_kernel()
{
    __shared__ int cnt[E];
    __shared__ int st[E + 1];
    __shared__ int cur[E];
    int tid = threadIdx.x;
    if (tid < E) cnt[tid] = 0;
    __syncthreads();
    for (int a = tid; a < NA; a += 256) atomicAdd(&cnt[g_topk_idx[a]], 1);
    __syncthreads();
    if (tid == 0) {
        int run = 0;
        for (int e2 = 0; e2 < E; e2++) { st[e2] = run; run += cnt[e2]; }
        st[E] = run;
    }
    __syncthreads();
    if (tid < E) cur[tid] = st[tid];
    if (tid <= E) g_seg_start[tid] = st[tid];
    __syncthreads();
    for (int a = tid; a < NA; a += 256) {
        int e2 = g_topk_idx[a];
        int pos = atomicAdd(&cur[e2], 1);
        g_perm_a[pos] = a;
        g_perm_score[pos] = g_topk_score[a];
    }
}

// ---------------- kernel 3: V = relu(X_e @ W1_e + b1_e) ----------------
// grid (2 hc, 64 e, 8 z), 128 thr, chunk = 16 tokens.
// warp = 4 tokens, lane = 4 h. x pre-duplicated (v,v) in smem, broadcast
// LDS.128 (2 tokens per load). Inner kk: 3 LDS.128 + 8 FFMA2.
__global__ __launch_bounds__(128, 4) void ffn1_kernel(
    const float* __restrict__ w1s, const float* __restrict__ b1s,
    const float* __restrict__ x)
{
    __shared__ __align__(16) float ws[32][132];  // [i 32][h 128 + 4] 16.9 KB
    __shared__ __align__(16) u64 xd[32][18];     // (x,x) dup [i][tok]  4.5 KB
    __shared__ int tok[16];
    int e = blockIdx.y, hc = blockIdx.x, z = blockIdx.z;
    int s = g_seg_start[e];
    int cnt = g_seg_start[e + 1] - s;
    int tid = threadIdx.x;
    int w = tid >> 5, l = tid & 31;
    const float* wbase = w1s + (size_t)e * IW * H + hc * 128;

    int wr[8], wc[8];
#pragma unroll
    for (int q = 0; q < 8; q++) {
        int f4 = tid + 128 * q;                  // 1024 float4s
        wr[q] = f4 >> 5; wc[q] = (f4 & 31) * 4;
    }
    int xt[4], xi[4];
#pragma unroll
    for (int q = 0; q < 4; q++) {
        int id = tid + 128 * q;                  // 512 entries
        xt[q] = id >> 5; xi[q] = id & 31;
    }

    for (int c0 = z * 16; c0 < cnt; c0 += 128) {
        int nt = min(16, cnt - c0);
        __syncthreads();
        if (tid < 16) tok[tid] = (tid < nt) ? (g_perm_a[s + c0 + tid] >> 1) : -1;
        __syncthreads();

        float4 pw[8]; float px[4];
#pragma unroll
        for (int q = 0; q < 8; q++)
            pw[q] = *(const float4*)(wbase + (size_t)wr[q] * H + wc[q]);
#pragma unroll
        for (int q = 0; q < 4; q++) {
            int tk = tok[xt[q]];
            px[q] = (tk >= 0) ? x[tk * IW + xi[q]] : 0.f;
        }

        u64 acc[4][2];
        float4 bv = *(const float4*)(b1s + e * H + hc * 128 + l * 4);
#pragma unroll
        for (int j = 0; j < 4; j++) {
            acc[j][0] = pack2(bv.x, bv.y);
            acc[j][1] = pack2(bv.z, bv.w);
        }

        for (int i0 = 0; i0 < IW; i0 += 32) {
#pragma unroll
            for (int q = 0; q < 8; q++)
                *(float4*)&ws[wr[q]][wc[q]] = pw[q];
#pragma unroll
            for (int q = 0; q < 4; q++)
                xd[xi[q]][xt[q]] = pack2(px[q], px[q]);
            __syncthreads();

            if (i0 + 32 < IW) {
                const float* wb = wbase + (size_t)(i0 + 32) * H;
#pragma unroll
                for (int q = 0; q < 8; q++)
                    pw[q] = *(const float4*)(wb + (size_t)wr[q] * H + wc[q]);
#pragma unroll
                for (int q = 0; q < 4; q++) {
                    int tk = tok[xt[q]];
                    px[q] = (tk >= 0) ? x[tk * IW + i0 + 32 + xi[q]] : 0.f;
                }
            }
#pragma unroll
            for (int kk = 0; kk < 32; kk++) {
                ulonglong2 wl = *(ulonglong2*)&ws[kk][l * 4];
                ulonglong2 xa = *(ulonglong2*)&xd[kk][w * 4];      // tok 4w,4w+1
                ulonglong2 xb = *(ulonglong2*)&xd[kk][w * 4 + 2];  // tok 4w+2,4w+3
                ffma2(acc[0][0], xa.x, wl.x); ffma2(acc[0][1], xa.x, wl.y);
                ffma2(acc[1][0], xa.y, wl.x); ffma2(acc[1][1], xa.y, wl.y);
                ffma2(acc[2][0], xb.x, wl.x); ffma2(acc[2][1], xb.x, wl.y);
                ffma2(acc[3][0], xb.y, wl.x); ffma2(acc[3][1], xb.y, wl.y);
            }
            __syncthreads();
        }

#pragma unroll
        for (int j = 0; j < 4; j++) {
            int t = w * 4 + j;
            if (t < nt) {
                float2 a0 = unpack2(acc[j][0]), a1 = unpack2(acc[j][1]);
                float4 o;
                o.x = fmaxf(a0.x, 0.f); o.y = fmaxf(a0.y, 0.f);
                o.z = fmaxf(a1.x, 0.f); o.w = fmaxf(a1.y, 0.f);
                *(float4*)&g_V[(size_t)(s + c0 + t) * H + hc * 128 + l * 4] = o;
            }
        }
    }
}

// ---------------- kernel 4: out += score * (V_e @ W2_e + b2_e) ----------------
// grid (4 oc, 64 e, 8 z), 128 thr, chunk = 16 tokens.
// warp = 4 tokens, lane = 4 o. Same broadcast-LDS.128 scheme; atomic epilogue
// (2 commutative adds per out element -> deterministic).
__global__ __launch_bounds__(128, 4) void ffn2_kernel(
    const float* __restrict__ w2s, const float* __restrict__ b2s,
    float* __restrict__ out)
{
    __shared__ __align__(16) float ws2[32][132]; // [h 32][o 128 + 4] 16.9 KB
    __shared__ __align__(16) u64 vd[32][18];     // (v,v) dup [h][tok] 4.5 KB
    int e = blockIdx.y, oc = blockIdx.x, z = blockIdx.z;
    int s = g_seg_start[e];
    int cnt = g_seg_start[e + 1] - s;
    int tid = threadIdx.x;
    int w = tid >> 5, l = tid & 31;
    const float* wbase = w2s + (size_t)e * H * OW + oc * 128;

    int wr[8], wc[8];
#pragma unroll
    for (int q = 0; q < 8; q++) {
        int f4 = tid + 128 * q;
        wr[q] = f4 >> 5; wc[q] = (f4 & 31) * 4;
    }
    int vt[4], vh[4];
#pragma unroll
    for (int q = 0; q < 4; q++) {
        int id = tid + 128 * q;
        vt[q] = id >> 5; vh[q] = id & 31;
    }

    for (int c0 = z * 16; c0 < cnt; c0 += 128) {
        int nt = min(16, cnt - c0);
        __syncthreads();

        float4 pw[8]; float pv[4];
#pragma unroll
        for (int q = 0; q < 8; q++)
            pw[q] = *(const float4*)(wbase + (size_t)wr[q] * OW + wc[q]);
#pragma unroll
        for (int q = 0; q < 4; q++)
            pv[q] = (vt[q] < nt) ? g_V[(size_t)(s + c0 + vt[q]) * H + vh[q]] : 0.f;

        u64 acc[4][2];
        float4 bv = *(const float4*)(b2s + e * OW + oc * 128 + l * 4);
#pragma unroll
        for (int j = 0; j < 4; j++) {
            acc[j][0] = pack2(bv.x, bv.y);
            acc[j][1] = pack2(bv.z, bv.w);
        }

        for (int h0 = 0; h0 < H; h0 += 32) {
#pragma unroll
            for (int q = 0; q < 8; q++)
                *(float4*)&ws2[wr[q]][wc[q]] = pw[q];
#pragma unroll
            for (int q = 0; q < 4; q++)
                vd[vh[q]][vt[q]] = pack2(pv[q], pv[q]);
            __syncthreads();

            if (h0 + 32 < H) {
                const float* wb = wbase + (size_t)(h0 + 32) * OW;
#pragma unroll
                for (int q = 0; q < 8; q++)
                    pw[q] = *(const float4*)(wb + (size_t)wr[q] * OW + wc[q]);
#pragma unroll
                for (int q = 0; q < 4; q++)
                    pv[q] = (vt[q] < nt) ?
                        g_V[(size_t)(s + c0 + vt[q]) * H + h0 + 32 + vh[q]] : 0.f;
            }
#pragma unroll
            for (int kk = 0; kk < 32; kk++) {
                ulonglong2 wl = *(ulonglong2*)&ws2[kk][l * 4];
                ulonglong2 va = *(ulonglong2*)&vd[kk][w * 4];
                ulonglong2 vb = *(ulonglong2*)&vd[kk][w * 4 + 2];
                ffma2(acc[0][0], va.x, wl.x); ffma2(acc[0][1], va.x, wl.y);
                ffma2(acc[1][0], va.y, wl.x); ffma2(acc[1][1], va.y, wl.y);
                ffma2(acc[2][0], vb.x, wl.x); ffma2(acc[2][1], vb.x, wl.y);
                ffma2(acc[3][0], vb.y, wl.x); ffma2(acc[3][1], vb.y, wl.y);
            }
            __syncthreads();
        }

#pragma unroll
        for (int j = 0; j < 4; j++) {
            int t = w * 4 + j;
            if (t < nt) {
                int   a  = g_perm_a[s + c0 + t];
                float sc = g_perm_score[s + c0 + t];
                int   tk = a >> 1;
                float* dst = out + (size_t)tk * OW + oc * 128 + l * 4;
                float2 f0 = unpack2(acc[j][0]), f1 = unpack2(acc[j][1]);
                atomicAdd(dst + 0, sc * f0.x);
                atomicAdd(dst + 1, sc * f0.y);
                atomicAdd(dst + 2, sc * f1.x);
                atomicAdd(dst + 3, sc * f1.y);
            }
        }
    }
}

// ---------------- launcher ----------------
extern "C" void kernel_launch(void* const* d_in, const int* in_sizes, int n_in,
                              void* d_out, int out_size)
{
    const float* x     = (const float*)d_in[0];
    const float* noise = (const float*)d_in[1];
    const float* w1s   = (const float*)d_in[2];
    const float* b1s   = (const float*)d_in[3];
    const float* w2s   = (const float*)d_in[4];
    const float* b2s   = (const float*)d_in[5];
    const float* mixer = (const float*)d_in[6];
    const float* nctl  = (const float*)d_in[7];

    zero_kernel<<<512, 256>>>((float4*)d_out);
    routing_kernel<<<128, 256>>>(x, noise, mixer, nctl);
    group_kernel<<<1, 256>>>();
    ffn1_kernel<<<dim3(2, 64, 8), 128>>>(w1s, b1s, x);
    ffn2_kernel<<<dim3(4, 64, 8), 128>>>(w2s, b2s, (float*)d_out);
}